// round 12
// baseline (speedup 1.0000x reference)
#include <cuda_runtime.h>
#include <cuda_bf16.h>

#define B_  128
#define T_  256
#define R_  1024
#define NU_ 256
#define BR_ (B_*R_)
#define KEXT 3072

typedef unsigned long long u64;
typedef unsigned int u32;

// ---------------- static device scratch ----------------
__device__ float g_xh[(size_t)T_*BR_];    // [t][r][b]
__device__ float g_xt[(size_t)T_*BR_];    // [t][r][b]
__device__ float g_hist[(size_t)T_*BR_];  // [t][r][b]
__device__ float g_sA[BR_];
__device__ float g_sB[BR_];
__device__ float g_s0[BR_];               // zeros
// extended-K bf16 weights: [mat][n][3072] = [W_hi | W_lo | W_hi] along k
__device__ __nv_bfloat16 g_wq[6u*1024u*KEXT];
// bf16 split state ping-pong, [m][k] row-major
__device__ __nv_bfloat16 g_shi[2][BR_];
__device__ __nv_bfloat16 g_slo[2][BR_];
__device__ __nv_bfloat16 g_shz[BR_];      // zeros
__device__ __nv_bfloat16 g_slz[BR_];      // zeros

// ---------------- helpers ----------------
__device__ __forceinline__ u64 pk2(float lo, float hi) {
    u64 r; asm("mov.b64 %0, {%1, %2};" : "=l"(r) : "f"(lo), "f"(hi)); return r;
}
__device__ __forceinline__ void up2(float &lo, float &hi, u64 v) {
    asm("mov.b64 {%0, %1}, %2;" : "=f"(lo), "=f"(hi) : "l"(v));
}
__device__ __forceinline__ void fma2(u64 &d, u64 a, u64 b) {
    asm("fma.rn.f32x2 %0, %1, %2, %0;" : "+l"(d) : "l"(a), "l"(b));
}
__device__ __forceinline__ float sigmoid_(float x) { return __frcp_rn(1.f + __expf(-x)); }
__device__ __forceinline__ float tanh_(float x) {
    return __fmaf_rn(2.f, __frcp_rn(1.f + __expf(-2.f*x)), -1.f);
}
__device__ __forceinline__ void cp16(unsigned s, const void* g) {
    asm volatile("cp.async.cg.shared.global [%0], [%1], 16;" :: "r"(s), "l"(g));
}
__device__ __forceinline__ void cpcommit() { asm volatile("cp.async.commit_group;"); }
template<int N> __device__ __forceinline__ void cpwait() {
    asm volatile("cp.async.wait_group %0;" :: "n"(N));
}
__device__ __forceinline__ u32 smem_u32(const void* p) {
    u32 a; asm("{ .reg .u64 t; cvta.to.shared.u64 t, %1; cvt.u32.u64 %0, t; }" : "=r"(a) : "l"(p));
    return a;
}

#define LDM4(r0,r1,r2,r3,addr) \
    asm volatile("ldmatrix.sync.aligned.m8n8.x4.shared.b16 {%0,%1,%2,%3}, [%4];" \
        : "=r"(r0),"=r"(r1),"=r"(r2),"=r"(r3) : "r"(addr))

#define MMA16816(c0,c1,c2,c3,a0,a1,a2,a3,b0,b1) \
    asm volatile("mma.sync.aligned.m16n8k16.row.col.f32.bf16.bf16.f32 " \
        "{%0,%1,%2,%3}, {%4,%5,%6,%7}, {%8,%9}, {%0,%1,%2,%3};" \
        : "+f"(c0),"+f"(c1),"+f"(c2),"+f"(c3) \
        : "r"(a0),"r"(a1),"r"(a2),"r"(a3),"r"(b0),"r"(b1))

// =================================================================================
// Stage kernel (mma.sync bf16): one highway layer.
// A_ext = [s_hi | s_hi | s_lo] (128 x 3072), B = per-gate [n][3072] = [Whi|Wlo|Whi].
// Grid 64 x 16 n-cols. 512 threads = 16 warps = (mw 8) x (nh 2); warp 16m x 16n.
// K streamed in 24 chunks of 128; 4-deep cp.async prefetch (3 chunks ahead).
// =================================================================================
#define KC 128
#define NCH 24
#define PITCH 272
#define A_BYTES (128*PITCH)       // 34816
#define B_BYTES (32*PITCH)        // 8704
#define BUF_BYTES (A_BYTES + B_BYTES)
#define SM_A(p) ((p)*BUF_BYTES)
#define SM_B(p) ((p)*BUF_BYTES + A_BYTES)
#define SM_TOTAL (4*BUF_BYTES)    // 174080

__global__ __launch_bounds__(512, 1)
void stage_tc(const float* __restrict__ s_in,
              const __nv_bfloat16* __restrict__ shi_in,
              const __nv_bfloat16* __restrict__ slo_in,
              const __nv_bfloat16* __restrict__ wh_ext,
              const __nv_bfloat16* __restrict__ wt_ext,
              const float* __restrict__ addh, const float* __restrict__ addt,
              int per_elem,
              float* __restrict__ s_out,
              __nv_bfloat16* __restrict__ shi_out,
              __nv_bfloat16* __restrict__ slo_out)
{
    extern __shared__ char sm[];
    const int tid  = threadIdx.x;
    const int warp = tid >> 5, lane = tid & 31;
    const int n0   = blockIdx.x * 16;
    const int mw   = warp >> 1;          // m-warp: rows mw*16 .. mw*16+15
    const int nh   = warp & 1;           // 0: h-gate B rows 0-15; 1: t-gate rows 16-31
    const int M0   = mw * 16;
    const u32 smb  = smem_u32(sm);

    // ---------------- chunk loader ----------------
    auto load_chunk = [&](int c, int p) {
        const int seg = c >> 3;                 // 0,1 -> s_hi ; 2 -> s_lo
        const int k0  = (c & 7) * KC;
        const __nv_bfloat16* asrc = (seg == 2) ? slo_in : shi_in;
        #pragma unroll
        for (int it = 0; it < 4; ++it) {        // A: 2048 cp16
            int idx = tid + it*512;
            int m = idx >> 4, kin = (idx & 15) * 8;
            cp16(smb + SM_A(p) + m*PITCH + kin*2,
                 asrc + (size_t)m*R_ + k0 + kin);
        }
        {                                        // B: 512 cp16
            int row = tid >> 4, kin = (tid & 15) * 8;
            const __nv_bfloat16* bsrc = (row < 16) ? wh_ext : wt_ext;
            cp16(smb + SM_B(p) + row*PITCH + kin*2,
                 bsrc + (size_t)(n0 + (row & 15))*KEXT + c*KC + kin);
        }
        cpcommit();
    };

    load_chunk(0, 0);
    load_chunk(1, 1);
    load_chunk(2, 2);

    float acc[8];
    #pragma unroll
    for (int a = 0; a < 8; ++a) acc[a] = 0.f;

    const u32 arow = (M0 + (lane & 15))*PITCH + (lane >> 4)*16;
    const u32 brow = (nh*16 + (lane & 15))*PITCH + (lane >> 4)*16;

    for (int c = 0; c < NCH; ++c) {
        if (c + 3 <= NCH)      cpwait<2>();
        else if (c + 2 == NCH) cpwait<1>();
        else                   cpwait<0>();
        __syncthreads();
        if (c + 3 < NCH) load_chunk(c + 3, (c + 3) & 3);

        const int p = c & 3;
        const u32 abase = smb + SM_A(p) + arow;
        const u32 bbase = smb + SM_B(p) + brow;
        #pragma unroll
        for (int ks = 0; ks < 8; ++ks) {
            u32 a0,a1,a2,a3, b0,b1,b2,b3;
            LDM4(a0,a1,a2,a3, abase + ks*32);
            LDM4(b0,b1,b2,b3, bbase + ks*32);
            MMA16816(acc[0], acc[1], acc[2], acc[3], a0,a1,a2,a3, b0,b2);
            MMA16816(acc[4], acc[5], acc[6], acc[7], a0,a1,a2,a3, b1,b3);
        }
    }
    __syncthreads();   // all reads done; buffers reusable for staging

    // ---------------- stage D to smem (Gsm aliases A buf0) ----------------
    float* Gsm = (float*)(sm + SM_A(0));        // [128][34]: cols 0-15 h, 16-31 t
    {
        const int r = lane >> 2, cb = (lane & 3)*2;
        #pragma unroll
        for (int nt = 0; nt < 2; ++nt) {
            *(float2*)&Gsm[(M0 + r)*34 + nh*16 + nt*8 + cb]     = make_float2(acc[nt*4+0], acc[nt*4+1]);
            *(float2*)&Gsm[(M0 + r + 8)*34 + nh*16 + nt*8 + cb] = make_float2(acc[nt*4+2], acc[nt*4+3]);
        }
    }
    __syncthreads();

    // ---------------- highway epilogue (coalesced) ----------------
    float* Ssm = (float*)(sm + SM_B(0));        // [128][17]
    {
        const int m = tid & 127, jq = tid >> 7;  // jq: 0..3, each 4 j's
        #pragma unroll
        for (int jj = 0; jj < 4; ++jj) {
            int j = jq*4 + jj;
            int n = n0 + j;
            float gh = Gsm[m*34 + j];
            float gt = Gsm[m*34 + 16 + j];
            float ah = per_elem ? addh[(size_t)n*128 + m] : addh[n];
            float at = per_elem ? addt[(size_t)n*128 + m] : addt[n];
            float so = s_in[(size_t)n*128 + m];
            float h  = tanh_(gh + ah);
            float tg = sigmoid_(gt + at);
            float sn = (h - so)*tg + so;
            s_out[(size_t)n*128 + m] = sn;
            Ssm[m*17 + j] = sn;
        }
    }
    __syncthreads();

    // ---------------- bf16 hi/lo write ([m][k], 32B per row) ----------------
    if (tid < 128) {
        const int m = tid;
        u32 uh[8], ul[8];
        #pragma unroll
        for (int j = 0; j < 16; ++j) {
            float sn = Ssm[m*17 + j];
            __nv_bfloat16 hi = __float2bfloat16(sn);
            __nv_bfloat16 lo = __float2bfloat16(sn - __bfloat162float(hi));
            unsigned short hs = __bfloat16_as_ushort(hi);
            unsigned short ls = __bfloat16_as_ushort(lo);
            if (j & 1) { uh[j >> 1] |= ((u32)hs) << 16; ul[j >> 1] |= ((u32)ls) << 16; }
            else       { uh[j >> 1]  = hs;              ul[j >> 1]  = ls; }
        }
        *(uint4*)(shi_out + (size_t)m*R_ + n0)     = make_uint4(uh[0], uh[1], uh[2], uh[3]);
        *(uint4*)(shi_out + (size_t)m*R_ + n0 + 8) = make_uint4(uh[4], uh[5], uh[6], uh[7]);
        *(uint4*)(slo_out + (size_t)m*R_ + n0)     = make_uint4(ul[0], ul[1], ul[2], ul[3]);
        *(uint4*)(slo_out + (size_t)m*R_ + n0 + 8) = make_uint4(ul[4], ul[5], ul[6], ul[7]);
    }
}

// =================================================================================
// Weight prep: transpose + bf16 hi/lo split into extended-K layout [n][3072].
// =================================================================================
__global__ __launch_bounds__(256, 1) void wprep(
    const float* __restrict__ W0, const float* __restrict__ W1,
    const float* __restrict__ W2, const float* __restrict__ W3,
    const float* __restrict__ W4, const float* __restrict__ W5)
{
    __shared__ float tile[32][33];
    const int z = blockIdx.z;
    const float* W = (z == 0) ? W0 : (z == 1) ? W1 : (z == 2) ? W2
                   : (z == 3) ? W3 : (z == 4) ? W4 : W5;
    const int k0 = blockIdx.x * 32, n0 = blockIdx.y * 32;
    const int tx = threadIdx.x & 31, ty = threadIdx.x >> 5;
    #pragma unroll
    for (int r = 0; r < 4; ++r) {
        int kk = ty + r*8;
        tile[kk][tx] = W[(size_t)(k0 + kk)*R_ + n0 + tx];
    }
    __syncthreads();
    #pragma unroll
    for (int r = 0; r < 4; ++r) {
        int nn = ty + r*8;
        float v = tile[tx][nn];
        __nv_bfloat16 hi = __float2bfloat16(v);
        __nv_bfloat16 lo = __float2bfloat16(v - __bfloat162float(hi));
        size_t base = (size_t)z*1024u*KEXT + (size_t)(n0 + nn)*KEXT;
        g_wq[base + k0 + tx]        = hi;
        g_wq[base + 1024 + k0 + tx] = lo;
        g_wq[base + 2048 + k0 + tx] = hi;
    }
}

// =================================================================================
// Pre kernel: xh = emb[tok]@Wh0x + bh0 ; xt likewise, stored [t][r][b].
// =================================================================================
#define KBP 8
__global__ __launch_bounds__(256, 1) void pre_kernel(
    const int* __restrict__ tok, const float* __restrict__ emb,
    const float* __restrict__ Whx, const float* __restrict__ Wtx,
    const float* __restrict__ bh, const float* __restrict__ bt)
{
    __shared__ float x_sm[NU_*34];
    __shared__ u64 wh_sm[KBP*64];
    __shared__ u64 wt_sm[KBP*64];

    const int tid  = threadIdx.x;
    const int row0 = blockIdx.y * 32;
    const int n0   = blockIdx.x * 64;

    #pragma unroll
    for (int it = 0; it < 8; ++it) {
        int idx = tid + it*256;
        int r = idx >> 6, q = idx & 63;
        int rho = row0 + r;
        int b = rho & (B_-1), t = rho >> 7;
        int token = tok[b*T_ + t];
        float4 v = *(const float4*)(emb + (size_t)token*NU_ + 4*q);
        x_sm[(4*q+0)*34 + r] = v.x;
        x_sm[(4*q+1)*34 + r] = v.y;
        x_sm[(4*q+2)*34 + r] = v.z;
        x_sm[(4*q+3)*34 + r] = v.w;
    }
    __syncthreads();

    const int mp = tid & 15;
    const int ng = tid >> 4;
    u64 acch[4] = {0,0,0,0};
    u64 acct[4] = {0,0,0,0};

    for (int k0 = 0; k0 < NU_; k0 += KBP) {
        #pragma unroll
        for (int it = 0; it < 2; ++it) {
            int idx = tid + it*256;
            int kl = idx >> 6, c = idx & 63;
            float wh = Whx[(size_t)(k0+kl)*R_ + n0 + c];
            float wt = Wtx[(size_t)(k0+kl)*R_ + n0 + c];
            wh_sm[kl*64 + c] = pk2(wh, wh);
            wt_sm[kl*64 + c] = pk2(wt, wt);
        }
        __syncthreads();
        #pragma unroll
        for (int kl = 0; kl < KBP; ++kl) {
            u64 x2 = *(const u64*)&x_sm[(k0+kl)*34 + 2*mp];
            ulonglong2 wa = *(const ulonglong2*)&wh_sm[kl*64 + 4*ng];
            ulonglong2 wb = *(const ulonglong2*)&wh_sm[kl*64 + 4*ng + 2];
            ulonglong2 ta = *(const ulonglong2*)&wt_sm[kl*64 + 4*ng];
            ulonglong2 tb = *(const ulonglong2*)&wt_sm[kl*64 + 4*ng + 2];
            fma2(acch[0], x2, wa.x); fma2(acch[1], x2, wa.y);
            fma2(acch[2], x2, wb.x); fma2(acch[3], x2, wb.y);
            fma2(acct[0], x2, ta.x); fma2(acct[1], x2, ta.y);
            fma2(acct[2], x2, tb.x); fma2(acct[3], x2, tb.y);
        }
        __syncthreads();
    }

    #pragma unroll
    for (int j = 0; j < 4; ++j) {
        int n = n0 + 4*ng + j;
        float lo, hi, tlo, thi;
        up2(lo, hi, acch[j]);
        up2(tlo, thi, acct[j]);
        int rho = row0 + 2*mp;
        int b = rho & (B_-1), t = rho >> 7;
        size_t base = (size_t)t*BR_ + (size_t)n*128 + b;
        g_xh[base]   = lo  + bh[n];
        g_xh[base+1] = hi  + bh[n];
        g_xt[base]   = tlo + bt[n];
        g_xt[base+1] = thi + bt[n];
    }
}

// =================================================================================
// Post kernel: out[(b*T+t), n] = sum_k hist[t][k][b] * Wp[k][n] + bp[n].
// =================================================================================
#define KBQ 32
__global__ __launch_bounds__(256, 1) void post_kernel(
    const float* __restrict__ Wp, const float* __restrict__ bp,
    float* __restrict__ out)
{
    __shared__ float s_sm[KBQ*32];
    __shared__ u64 w_sm[KBQ*64];

    const int tid = threadIdx.x;
    const int n0  = blockIdx.x * 64;
    const int b0  = blockIdx.y * 32;
    const int t   = blockIdx.z;
    const float* A = g_hist + (size_t)t*BR_;

    const int mp = tid & 15;
    const int ng = tid >> 4;
    u64 acc[4] = {0,0,0,0};

    for (int k0 = 0; k0 < R_; k0 += KBQ) {
        {
            int kl = tid >> 3, bl = (tid & 7) * 4;
            float4 v = *(const float4*)(A + (size_t)(k0+kl)*128 + b0 + bl);
            *(float4*)&s_sm[kl*32 + bl] = v;
        }
        #pragma unroll
        for (int it = 0; it < 4; ++it) {
            int idx = tid + it*256;
            int kl = idx >> 5, c = idx & 31;
            float2 wv = *(const float2*)(Wp + (size_t)(k0+kl)*NU_ + n0 + 2*c);
            w_sm[kl*64 + 2*c]   = pk2(wv.x, wv.x);
            w_sm[kl*64 + 2*c+1] = pk2(wv.y, wv.y);
        }
        __syncthreads();
        #pragma unroll 8
        for (int kl = 0; kl < KBQ; ++kl) {
            u64 s2 = *(const u64*)&s_sm[kl*32 + 2*mp];
            ulonglong2 wa = *(const ulonglong2*)&w_sm[kl*64 + 4*ng];
            ulonglong2 wb = *(const ulonglong2*)&w_sm[kl*64 + 4*ng + 2];
            fma2(acc[0], s2, wa.x); fma2(acc[1], s2, wa.y);
            fma2(acc[2], s2, wb.x); fma2(acc[3], s2, wb.y);
        }
        __syncthreads();
    }

    #pragma unroll
    for (int j = 0; j < 4; ++j) {
        int n = n0 + 4*ng + j;
        float lo, hi;
        up2(lo, hi, acc[j]);
        int bl = b0 + 2*mp;
        out[(size_t)(bl*T_ + t)*NU_ + n]     = lo + bp[n];
        out[(size_t)((bl+1)*T_ + t)*NU_ + n] = hi + bp[n];
    }
}

// =================================================================================
extern "C" void kernel_launch(void* const* d_in, const int* in_sizes, int n_in,
                              void* d_out, int out_size) {
    const int*   tok  = (const int*)  d_in[0];
    const float* emb  = (const float*)d_in[1];
    const float* Wh0x = (const float*)d_in[2];
    const float* Wh0s = (const float*)d_in[3];
    const float* bh0  = (const float*)d_in[4];
    const float* Wt0x = (const float*)d_in[5];
    const float* Wt0s = (const float*)d_in[6];
    const float* bt0  = (const float*)d_in[7];
    const float* Whh  = (const float*)d_in[8];
    const float* bhh  = (const float*)d_in[9];
    const float* Wth  = (const float*)d_in[10];
    const float* bth  = (const float*)d_in[11];
    const float* Wp   = (const float*)d_in[12];
    const float* bp   = (const float*)d_in[13];

    float *xh, *xt, *hist, *sA, *sB, *s0;
    __nv_bfloat16 *wq, *shi0, *slo0, *shz, *slz;
    cudaGetSymbolAddress((void**)&xh,   g_xh);
    cudaGetSymbolAddress((void**)&xt,   g_xt);
    cudaGetSymbolAddress((void**)&hist, g_hist);
    cudaGetSymbolAddress((void**)&sA,   g_sA);
    cudaGetSymbolAddress((void**)&sB,   g_sB);
    cudaGetSymbolAddress((void**)&s0,   g_s0);
    cudaGetSymbolAddress((void**)&wq,   g_wq);
    cudaGetSymbolAddress((void**)&shi0, g_shi);
    cudaGetSymbolAddress((void**)&slo0, g_slo);
    cudaGetSymbolAddress((void**)&shz,  g_shz);
    cudaGetSymbolAddress((void**)&slz,  g_slz);

    cudaFuncSetAttribute(stage_tc, cudaFuncAttributeMaxDynamicSharedMemorySize, SM_TOTAL);

    wprep<<<dim3(32, 32, 6), 256>>>(Wh0s, Wt0s, Whh, Wth,
                                    Whh + 1048576, Wth + 1048576);
    pre_kernel<<<dim3(16, 1024), 256>>>(tok, emb, Wh0x, Wt0x, bh0, bt0);

    const float* sf_in = s0;
    const __nv_bfloat16* bhi_in = shz;
    const __nv_bfloat16* blo_in = slz;
    int si = 0;
    for (int t = 0; t < T_; ++t) {
        for (int layer = 0; layer < 3; ++layer) {
            float* sf_out = (layer == 0) ? sA : (layer == 1) ? sB : hist + (size_t)t*BR_;
            int mh = (layer == 0) ? 0 : (layer == 1) ? 2 : 4;
            int mt = mh + 1;
            const float* ah = (layer == 0) ? xh + (size_t)t*BR_ : bhh + (layer-1)*R_;
            const float* at = (layer == 0) ? xt + (size_t)t*BR_ : bth + (layer-1)*R_;
            int pe = (layer == 0) ? 1 : 0;
            __nv_bfloat16* bhi_out = shi0 + (size_t)(si & 1)*BR_;
            __nv_bfloat16* blo_out = slo0 + (size_t)(si & 1)*BR_;
            stage_tc<<<64, 512, SM_TOTAL>>>(
                sf_in, bhi_in, blo_in,
                wq + (size_t)mh*1024u*KEXT,
                wq + (size_t)mt*1024u*KEXT,
                ah, at, pe, sf_out, bhi_out, blo_out);
            sf_in = sf_out; bhi_in = bhi_out; blo_in = blo_out;
            ++si;
        }
    }

    post_kernel<<<dim3(4, 4, 256), 256>>>(Wp, bp, (float*)d_out);
}

// round 15
// speedup vs baseline: 1.0090x; 1.0090x over previous
#include <cuda_runtime.h>
#include <cuda_bf16.h>

#define B_  128
#define T_  256
#define R_  1024
#define NU_ 256
#define BR_ (B_*R_)
#define KEXT 3072

typedef unsigned long long u64;
typedef unsigned int u32;

// ---------------- static device scratch ----------------
__device__ float g_xh[(size_t)T_*BR_];    // [t][r][b]
__device__ float g_xt[(size_t)T_*BR_];    // [t][r][b]
__device__ float g_hist[(size_t)T_*BR_];  // [t][r][b]
__device__ float g_sA[BR_];
__device__ float g_sB[BR_];
__device__ float g_s0[BR_];               // zeros
// extended-K bf16 weights: [mat][n][3072] = [W_hi | W_lo | W_hi] along k
__device__ __nv_bfloat16 g_wq[6u*1024u*KEXT];
// bf16 split state ping-pong, [m][k] row-major
__device__ __nv_bfloat16 g_shi[2][BR_];
__device__ __nv_bfloat16 g_slo[2][BR_];
__device__ __nv_bfloat16 g_shz[BR_];      // zeros
__device__ __nv_bfloat16 g_slz[BR_];      // zeros

// ---------------- helpers ----------------
__device__ __forceinline__ u64 pk2(float lo, float hi) {
    u64 r; asm("mov.b64 %0, {%1, %2};" : "=l"(r) : "f"(lo), "f"(hi)); return r;
}
__device__ __forceinline__ void up2(float &lo, float &hi, u64 v) {
    asm("mov.b64 {%0, %1}, %2;" : "=f"(lo), "=f"(hi) : "l"(v));
}
__device__ __forceinline__ void fma2(u64 &d, u64 a, u64 b) {
    asm("fma.rn.f32x2 %0, %1, %2, %0;" : "+l"(d) : "l"(a), "l"(b));
}
__device__ __forceinline__ float sigmoid_(float x) { return __frcp_rn(1.f + __expf(-x)); }
__device__ __forceinline__ float tanh_(float x) {
    return __fmaf_rn(2.f, __frcp_rn(1.f + __expf(-2.f*x)), -1.f);
}
__device__ __forceinline__ void cp16(unsigned s, const void* g) {
    asm volatile("cp.async.cg.shared.global [%0], [%1], 16;" :: "r"(s), "l"(g));
}
__device__ __forceinline__ void cpcommit() { asm volatile("cp.async.commit_group;"); }
template<int N> __device__ __forceinline__ void cpwait() {
    asm volatile("cp.async.wait_group %0;" :: "n"(N));
}
__device__ __forceinline__ u32 smem_u32(const void* p) {
    u32 a; asm("{ .reg .u64 t; cvta.to.shared.u64 t, %1; cvt.u32.u64 %0, t; }" : "=r"(a) : "l"(p));
    return a;
}

#define LDM4(r0,r1,r2,r3,addr) \
    asm volatile("ldmatrix.sync.aligned.m8n8.x4.shared.b16 {%0,%1,%2,%3}, [%4];" \
        : "=r"(r0),"=r"(r1),"=r"(r2),"=r"(r3) : "r"(addr))

#define MMA16816(c0,c1,c2,c3,a0,a1,a2,a3,b0,b1) \
    asm volatile("mma.sync.aligned.m16n8k16.row.col.f32.bf16.bf16.f32 " \
        "{%0,%1,%2,%3}, {%4,%5,%6,%7}, {%8,%9}, {%0,%1,%2,%3};" \
        : "+f"(c0),"+f"(c1),"+f"(c2),"+f"(c3) \
        : "r"(a0),"r"(a1),"r"(a2),"r"(a3),"r"(b0),"r"(b1))

// =================================================================================
// Stage kernel (mma.sync bf16): one highway layer.
// A_ext = [s_hi | s_hi | s_lo] (128 x 3072), B = per-gate [n][3072] = [Whi|Wlo|Whi].
// Grid 64 x 16 n-cols. 512 threads = 16 warps = (mw 8) x (nh 2); warp 16m x 16n.
// K streamed in 24 chunks of 128; 4-deep cp.async prefetch (3 chunks ahead).
// KEY CHANGE (R13): 4 rotating accumulator sets per n-chain (8 independent
// MMA chains/warp) to break the long HMMA RAW chain; merged at the end.
// =================================================================================
#define KC 128
#define NCH 24
#define PITCH 272
#define A_BYTES (128*PITCH)       // 34816
#define B_BYTES (32*PITCH)        // 8704
#define BUF_BYTES (A_BYTES + B_BYTES)
#define SM_A(p) ((p)*BUF_BYTES)
#define SM_B(p) ((p)*BUF_BYTES + A_BYTES)
#define SM_TOTAL (4*BUF_BYTES)    // 174080

__global__ __launch_bounds__(512, 1)
void stage_tc(const float* __restrict__ s_in,
              const __nv_bfloat16* __restrict__ shi_in,
              const __nv_bfloat16* __restrict__ slo_in,
              const __nv_bfloat16* __restrict__ wh_ext,
              const __nv_bfloat16* __restrict__ wt_ext,
              const float* __restrict__ addh, const float* __restrict__ addt,
              int per_elem,
              float* __restrict__ s_out,
              __nv_bfloat16* __restrict__ shi_out,
              __nv_bfloat16* __restrict__ slo_out)
{
    extern __shared__ char sm[];
    const int tid  = threadIdx.x;
    const int warp = tid >> 5, lane = tid & 31;
    const int n0   = blockIdx.x * 16;
    const int mw   = warp >> 1;          // m-warp: rows mw*16 .. mw*16+15
    const int nh   = warp & 1;           // 0: h-gate B rows 0-15; 1: t-gate rows 16-31
    const int M0   = mw * 16;
    const u32 smb  = smem_u32(sm);

    // ---------------- chunk loader ----------------
    auto load_chunk = [&](int c, int p) {
        const int seg = c >> 3;                 // 0,1 -> s_hi ; 2 -> s_lo
        const int k0  = (c & 7) * KC;
        const __nv_bfloat16* asrc = (seg == 2) ? slo_in : shi_in;
        #pragma unroll
        for (int it = 0; it < 4; ++it) {        // A: 2048 cp16
            int idx = tid + it*512;
            int m = idx >> 4, kin = (idx & 15) * 8;
            cp16(smb + SM_A(p) + m*PITCH + kin*2,
                 asrc + (size_t)m*R_ + k0 + kin);
        }
        {                                        // B: 512 cp16
            int row = tid >> 4, kin = (tid & 15) * 8;
            const __nv_bfloat16* bsrc = (row < 16) ? wh_ext : wt_ext;
            cp16(smb + SM_B(p) + row*PITCH + kin*2,
                 bsrc + (size_t)(n0 + (row & 15))*KEXT + c*KC + kin);
        }
        cpcommit();
    };

    load_chunk(0, 0);
    load_chunk(1, 1);
    load_chunk(2, 2);

    // 4 rotation sets x 2 n-chains x 4 regs = 32 independent accumulators
    float acc[4][8];
    #pragma unroll
    for (int r = 0; r < 4; ++r)
        #pragma unroll
        for (int a = 0; a < 8; ++a) acc[r][a] = 0.f;

    const u32 arow = (M0 + (lane & 15))*PITCH + (lane >> 4)*16;
    const u32 brow = (nh*16 + (lane & 15))*PITCH + (lane >> 4)*16;

    for (int c = 0; c < NCH; ++c) {
        if (c + 3 <= NCH)      cpwait<2>();
        else if (c + 2 == NCH) cpwait<1>();
        else                   cpwait<0>();
        __syncthreads();
        if (c + 3 < NCH) load_chunk(c + 3, (c + 3) & 3);

        const int p = c & 3;
        const u32 abase = smb + SM_A(p) + arow;
        const u32 bbase = smb + SM_B(p) + brow;
        #pragma unroll
        for (int ks = 0; ks < 8; ++ks) {
            const int rs = ks & 3;               // rotation set -> 4x shorter chains
            u32 a0,a1,a2,a3, b0,b1,b2,b3;
            LDM4(a0,a1,a2,a3, abase + ks*32);
            LDM4(b0,b1,b2,b3, bbase + ks*32);
            MMA16816(acc[rs][0], acc[rs][1], acc[rs][2], acc[rs][3], a0,a1,a2,a3, b0,b2);
            MMA16816(acc[rs][4], acc[rs][5], acc[rs][6], acc[rs][7], a0,a1,a2,a3, b1,b3);
        }
    }
    // merge rotation sets
    #pragma unroll
    for (int r = 1; r < 4; ++r)
        #pragma unroll
        for (int a = 0; a < 8; ++a) acc[0][a] += acc[r][a];
    __syncthreads();   // all reads done; buffers reusable for staging

    // ---------------- stage D to smem (Gsm aliases A buf0) ----------------
    float* Gsm = (float*)(sm + SM_A(0));        // [128][34]: cols 0-15 h, 16-31 t
    {
        const int r = lane >> 2, cb = (lane & 3)*2;
        #pragma unroll
        for (int nt = 0; nt < 2; ++nt) {
            *(float2*)&Gsm[(M0 + r)*34 + nh*16 + nt*8 + cb]     = make_float2(acc[0][nt*4+0], acc[0][nt*4+1]);
            *(float2*)&Gsm[(M0 + r + 8)*34 + nh*16 + nt*8 + cb] = make_float2(acc[0][nt*4+2], acc[0][nt*4+3]);
        }
    }
    __syncthreads();

    // ---------------- highway epilogue (coalesced) ----------------
    float* Ssm = (float*)(sm + SM_B(0));        // [128][17]
    {
        const int m = tid & 127, jq = tid >> 7;  // jq: 0..3, each 4 j's
        #pragma unroll
        for (int jj = 0; jj < 4; ++jj) {
            int j = jq*4 + jj;
            int n = n0 + j;
            float gh = Gsm[m*34 + j];
            float gt = Gsm[m*34 + 16 + j];
            float ah = per_elem ? addh[(size_t)n*128 + m] : addh[n];
            float at = per_elem ? addt[(size_t)n*128 + m] : addt[n];
            float so = s_in[(size_t)n*128 + m];
            float h  = tanh_(gh + ah);
            float tg = sigmoid_(gt + at);
            float sn = (h - so)*tg + so;
            s_out[(size_t)n*128 + m] = sn;
            Ssm[m*17 + j] = sn;
        }
    }
    __syncthreads();

    // ---------------- bf16 hi/lo write ([m][k], 32B per row) ----------------
    if (tid < 128) {
        const int m = tid;
        u32 uh[8], ul[8];
        #pragma unroll
        for (int j = 0; j < 16; ++j) {
            float sn = Ssm[m*17 + j];
            __nv_bfloat16 hi = __float2bfloat16(sn);
            __nv_bfloat16 lo = __float2bfloat16(sn - __bfloat162float(hi));
            unsigned short hs = __bfloat16_as_ushort(hi);
            unsigned short ls = __bfloat16_as_ushort(lo);
            if (j & 1) { uh[j >> 1] |= ((u32)hs) << 16; ul[j >> 1] |= ((u32)ls) << 16; }
            else       { uh[j >> 1]  = hs;              ul[j >> 1]  = ls; }
        }
        *(uint4*)(shi_out + (size_t)m*R_ + n0)     = make_uint4(uh[0], uh[1], uh[2], uh[3]);
        *(uint4*)(shi_out + (size_t)m*R_ + n0 + 8) = make_uint4(uh[4], uh[5], uh[6], uh[7]);
        *(uint4*)(slo_out + (size_t)m*R_ + n0)     = make_uint4(ul[0], ul[1], ul[2], ul[3]);
        *(uint4*)(slo_out + (size_t)m*R_ + n0 + 8) = make_uint4(ul[4], ul[5], ul[6], ul[7]);
    }
}

// =================================================================================
// Weight prep: transpose + bf16 hi/lo split into extended-K layout [n][3072].
// =================================================================================
__global__ __launch_bounds__(256, 1) void wprep(
    const float* __restrict__ W0, const float* __restrict__ W1,
    const float* __restrict__ W2, const float* __restrict__ W3,
    const float* __restrict__ W4, const float* __restrict__ W5)
{
    __shared__ float tile[32][33];
    const int z = blockIdx.z;
    const float* W = (z == 0) ? W0 : (z == 1) ? W1 : (z == 2) ? W2
                   : (z == 3) ? W3 : (z == 4) ? W4 : W5;
    const int k0 = blockIdx.x * 32, n0 = blockIdx.y * 32;
    const int tx = threadIdx.x & 31, ty = threadIdx.x >> 5;
    #pragma unroll
    for (int r = 0; r < 4; ++r) {
        int kk = ty + r*8;
        tile[kk][tx] = W[(size_t)(k0 + kk)*R_ + n0 + tx];
    }
    __syncthreads();
    #pragma unroll
    for (int r = 0; r < 4; ++r) {
        int nn = ty + r*8;
        float v = tile[tx][nn];
        __nv_bfloat16 hi = __float2bfloat16(v);
        __nv_bfloat16 lo = __float2bfloat16(v - __bfloat162float(hi));
        size_t base = (size_t)z*1024u*KEXT + (size_t)(n0 + nn)*KEXT;
        g_wq[base + k0 + tx]        = hi;
        g_wq[base + 1024 + k0 + tx] = lo;
        g_wq[base + 2048 + k0 + tx] = hi;
    }
}

// =================================================================================
// Pre kernel: xh = emb[tok]@Wh0x + bh0 ; xt likewise, stored [t][r][b].
// =================================================================================
#define KBP 8
__global__ __launch_bounds__(256, 1) void pre_kernel(
    const int* __restrict__ tok, const float* __restrict__ emb,
    const float* __restrict__ Whx, const float* __restrict__ Wtx,
    const float* __restrict__ bh, const float* __restrict__ bt)
{
    __shared__ float x_sm[NU_*34];
    __shared__ u64 wh_sm[KBP*64];
    __shared__ u64 wt_sm[KBP*64];

    const int tid  = threadIdx.x;
    const int row0 = blockIdx.y * 32;
    const int n0   = blockIdx.x * 64;

    #pragma unroll
    for (int it = 0; it < 8; ++it) {
        int idx = tid + it*256;
        int r = idx >> 6, q = idx & 63;
        int rho = row0 + r;
        int b = rho & (B_-1), t = rho >> 7;
        int token = tok[b*T_ + t];
        float4 v = *(const float4*)(emb + (size_t)token*NU_ + 4*q);
        x_sm[(4*q+0)*34 + r] = v.x;
        x_sm[(4*q+1)*34 + r] = v.y;
        x_sm[(4*q+2)*34 + r] = v.z;
        x_sm[(4*q+3)*34 + r] = v.w;
    }
    __syncthreads();

    const int mp = tid & 15;
    const int ng = tid >> 4;
    u64 acch[4] = {0,0,0,0};
    u64 acct[4] = {0,0,0,0};

    for (int k0 = 0; k0 < NU_; k0 += KBP) {
        #pragma unroll
        for (int it = 0; it < 2; ++it) {
            int idx = tid + it*256;
            int kl = idx >> 6, c = idx & 63;
            float wh = Whx[(size_t)(k0+kl)*R_ + n0 + c];
            float wt = Wtx[(size_t)(k0+kl)*R_ + n0 + c];
            wh_sm[kl*64 + c] = pk2(wh, wh);
            wt_sm[kl*64 + c] = pk2(wt, wt);
        }
        __syncthreads();
        #pragma unroll
        for (int kl = 0; kl < KBP; ++kl) {
            u64 x2 = *(const u64*)&x_sm[(k0+kl)*34 + 2*mp];
            ulonglong2 wa = *(const ulonglong2*)&wh_sm[kl*64 + 4*ng];
            ulonglong2 wb = *(const ulonglong2*)&wh_sm[kl*64 + 4*ng + 2];
            ulonglong2 ta = *(const ulonglong2*)&wt_sm[kl*64 + 4*ng];
            ulonglong2 tb = *(const ulonglong2*)&wt_sm[kl*64 + 4*ng + 2];
            fma2(acch[0], x2, wa.x); fma2(acch[1], x2, wa.y);
            fma2(acch[2], x2, wb.x); fma2(acch[3], x2, wb.y);
            fma2(acct[0], x2, ta.x); fma2(acct[1], x2, ta.y);
            fma2(acct[2], x2, tb.x); fma2(acct[3], x2, tb.y);
        }
        __syncthreads();
    }

    #pragma unroll
    for (int j = 0; j < 4; ++j) {
        int n = n0 + 4*ng + j;
        float lo, hi, tlo, thi;
        up2(lo, hi, acch[j]);
        up2(tlo, thi, acct[j]);
        int rho = row0 + 2*mp;
        int b = rho & (B_-1), t = rho >> 7;
        size_t base = (size_t)t*BR_ + (size_t)n*128 + b;
        g_xh[base]   = lo  + bh[n];
        g_xh[base+1] = hi  + bh[n];
        g_xt[base]   = tlo + bt[n];
        g_xt[base+1] = thi + bt[n];
    }
}

// =================================================================================
// Post kernel: out[(b*T+t), n] = sum_k hist[t][k][b] * Wp[k][n] + bp[n].
// =================================================================================
#define KBQ 32
__global__ __launch_bounds__(256, 1) void post_kernel(
    const float* __restrict__ Wp, const float* __restrict__ bp,
    float* __restrict__ out)
{
    __shared__ float s_sm[KBQ*32];
    __shared__ u64 w_sm[KBQ*64];

    const int tid = threadIdx.x;
    const int n0  = blockIdx.x * 64;
    const int b0  = blockIdx.y * 32;
    const int t   = blockIdx.z;
    const float* A = g_hist + (size_t)t*BR_;

    const int mp = tid & 15;
    const int ng = tid >> 4;
    u64 acc[4] = {0,0,0,0};

    for (int k0 = 0; k0 < R_; k0 += KBQ) {
        {
            int kl = tid >> 3, bl = (tid & 7) * 4;
            float4 v = *(const float4*)(A + (size_t)(k0+kl)*128 + b0 + bl);
            *(float4*)&s_sm[kl*32 + bl] = v;
        }
        #pragma unroll
        for (int it = 0; it < 4; ++it) {
            int idx = tid + it*256;
            int kl = idx >> 5, c = idx & 31;
            float2 wv = *(const float2*)(Wp + (size_t)(k0+kl)*NU_ + n0 + 2*c);
            w_sm[kl*64 + 2*c]   = pk2(wv.x, wv.x);
            w_sm[kl*64 + 2*c+1] = pk2(wv.y, wv.y);
        }
        __syncthreads();
        #pragma unroll 8
        for (int kl = 0; kl < KBQ; ++kl) {
            u64 s2 = *(const u64*)&s_sm[kl*32 + 2*mp];
            ulonglong2 wa = *(const ulonglong2*)&w_sm[kl*64 + 4*ng];
            ulonglong2 wb = *(const ulonglong2*)&w_sm[kl*64 + 4*ng + 2];
            fma2(acc[0], s2, wa.x); fma2(acc[1], s2, wa.y);
            fma2(acc[2], s2, wb.x); fma2(acc[3], s2, wb.y);
        }
        __syncthreads();
    }

    #pragma unroll
    for (int j = 0; j < 4; ++j) {
        int n = n0 + 4*ng + j;
        float lo, hi;
        up2(lo, hi, acc[j]);
        int bl = b0 + 2*mp;
        out[(size_t)(bl*T_ + t)*NU_ + n]     = lo + bp[n];
        out[(size_t)((bl+1)*T_ + t)*NU_ + n] = hi + bp[n];
    }
}

// =================================================================================
extern "C" void kernel_launch(void* const* d_in, const int* in_sizes, int n_in,
                              void* d_out, int out_size) {
    const int*   tok  = (const int*)  d_in[0];
    const float* emb  = (const float*)d_in[1];
    const float* Wh0x = (const float*)d_in[2];
    const float* Wh0s = (const float*)d_in[3];
    const float* bh0  = (const float*)d_in[4];
    const float* Wt0x = (const float*)d_in[5];
    const float* Wt0s = (const float*)d_in[6];
    const float* bt0  = (const float*)d_in[7];
    const float* Whh  = (const float*)d_in[8];
    const float* bhh  = (const float*)d_in[9];
    const float* Wth  = (const float*)d_in[10];
    const float* bth  = (const float*)d_in[11];
    const float* Wp   = (const float*)d_in[12];
    const float* bp   = (const float*)d_in[13];

    float *xh, *xt, *hist, *sA, *sB, *s0;
    __nv_bfloat16 *wq, *shi0, *slo0, *shz, *slz;
    cudaGetSymbolAddress((void**)&xh,   g_xh);
    cudaGetSymbolAddress((void**)&xt,   g_xt);
    cudaGetSymbolAddress((void**)&hist, g_hist);
    cudaGetSymbolAddress((void**)&sA,   g_sA);
    cudaGetSymbolAddress((void**)&sB,   g_sB);
    cudaGetSymbolAddress((void**)&s0,   g_s0);
    cudaGetSymbolAddress((void**)&wq,   g_wq);
    cudaGetSymbolAddress((void**)&shi0, g_shi);
    cudaGetSymbolAddress((void**)&slo0, g_slo);
    cudaGetSymbolAddress((void**)&shz,  g_shz);
    cudaGetSymbolAddress((void**)&slz,  g_slz);

    cudaFuncSetAttribute(stage_tc, cudaFuncAttributeMaxDynamicSharedMemorySize, SM_TOTAL);

    wprep<<<dim3(32, 32, 6), 256>>>(Wh0s, Wt0s, Whh, Wth,
                                    Whh + 1048576, Wth + 1048576);
    pre_kernel<<<dim3(16, 1024), 256>>>(tok, emb, Wh0x, Wt0x, bh0, bt0);

    const float* sf_in = s0;
    const __nv_bfloat16* bhi_in = shz;
    const __nv_bfloat16* blo_in = slz;
    int si = 0;
    for (int t = 0; t < T_; ++t) {
        for (int layer = 0; layer < 3; ++layer) {
            float* sf_out = (layer == 0) ? sA : (layer == 1) ? sB : hist + (size_t)t*BR_;
            int mh = (layer == 0) ? 0 : (layer == 1) ? 2 : 4;
            int mt = mh + 1;
            const float* ah = (layer == 0) ? xh + (size_t)t*BR_ : bhh + (layer-1)*R_;
            const float* at = (layer == 0) ? xt + (size_t)t*BR_ : bth + (layer-1)*R_;
            int pe = (layer == 0) ? 1 : 0;
            __nv_bfloat16* bhi_out = shi0 + (size_t)(si & 1)*BR_;
            __nv_bfloat16* blo_out = slo0 + (size_t)(si & 1)*BR_;
            stage_tc<<<64, 512, SM_TOTAL>>>(
                sf_in, bhi_in, blo_in,
                wq + (size_t)mh*1024u*KEXT,
                wq + (size_t)mt*1024u*KEXT,
                ah, at, pe, sf_out, bhi_out, blo_out);
            sf_in = sf_out; bhi_in = bhi_out; blo_in = blo_out;
            ++si;
        }
    }

    post_kernel<<<dim3(4, 4, 256), 256>>>(Wp, bp, (float*)d_out);
}